// round 4
// baseline (speedup 1.0000x reference)
#include <cuda_runtime.h>
#include <cuda_bf16.h>
#include <math.h>

// ---------------------------------------------------------------------------
// SHINE heterogeneous GCN, fused pipeline.
// Sizes (fixed by the problem):
#define N_DOC   10000
#define N_WORD  20000
#define N_ENT   10000
#define N_POS   60
#define DIM     128
#define D_POS_IN 60
#define D_WEMB  300
#define EPSN    1e-9f

// ---------------- scratch layout (floats) ----------------
// Accumulator region (must be zeroed each call), then gemm outputs.
#define TMPA_OFF   0                               // spmm(a11,f1)    20000x128
#define TMPB_OFF   (TMPA_OFF  + N_WORD*DIM)        // spmm(a11,g1)    20000x128
#define TMP2_OFF   (TMPB_OFF  + N_WORD*DIM)        // spmm(a22,f2)    10000x128
#define TMP2B_OFF  (TMP2_OFF  + N_ENT*DIM)         // spmm(a22,g2)    10000x128
#define TMP3_OFF   (TMP2B_OFF + N_ENT*DIM)         // spmm(a33,g3)       60x128
#define TMP3B_OFF  (TMP3_OFF  + N_POS*DIM)         // spmm(a33,g3b)      60x128
#define ACC_TOTAL  (TMP3B_OFF + N_POS*DIM)
#define G1_OFF     ACC_TOTAL                       // relu(tmpA)@W1_2+b  20000x128
#define G2_OFF     (G1_OFF + N_WORD*DIM)           // 10000x128
#define G3_OFF     (G2_OFF + N_ENT*DIM)            // f3@W3+b3  60x128
#define G3B_OFF    (G3_OFF + N_POS*DIM)            // 60x128
#define SCRATCH_TOTAL (G3B_OFF + N_POS*DIM)

__device__ __align__(16) float g_scratch[SCRATCH_TOTAL];

// output layout in d_out (floats)
#define OUT1_OFF 0
#define OUT2_OFF (N_DOC*DIM)                       // 1,280,000
#define OUT3_OFF (OUT2_OFF + N_DOC*(DIM + D_WEMB)) // 5,560,000
#define OUT2_STRIDE (DIM + D_WEMB)                 // 428

// ---------------------------------------------------------------------------
// vectorized global reduction (sm_90+): no return value, no read-back.
__device__ __forceinline__ void red_add_v4(float* addr, float4 v) {
    asm volatile("red.global.add.v4.f32 [%0], {%1, %2, %3, %4};"
                 :: "l"(addr), "f"(v.x), "f"(v.y), "f"(v.z), "f"(v.w)
                 : "memory");
}

// ---------------------------------------------------------------------------
// spmm scatter: out[rows[e], :] += vals[e] * (relu?)(x[cols[e], :])
// D = 128 fixed (32 float4, one per lane). Warp per edge.
template <bool RELU_SRC>
__global__ void scatter128_kernel(const int* __restrict__ rows,
                                  const int* __restrict__ cols,
                                  const float* __restrict__ vals,
                                  const float* __restrict__ x,
                                  float* __restrict__ out,
                                  int dst_stride, int E)
{
    int gw   = (blockIdx.x * blockDim.x + threadIdx.x) >> 5;
    int lane = threadIdx.x & 31;
    int nw   = (gridDim.x * blockDim.x) >> 5;
    for (int e = gw; e < E; e += nw) {
        int   r = __ldg(rows + e);
        int   c = __ldg(cols + e);
        float v = __ldg(vals + e);
        const float4* src = (const float4*)(x + (size_t)c * DIM);
        float4 t = __ldg(src + lane);
        if (RELU_SRC) {
            t.x = fmaxf(t.x, 0.f); t.y = fmaxf(t.y, 0.f);
            t.z = fmaxf(t.z, 0.f); t.w = fmaxf(t.w, 0.f);
        }
        float4 o = make_float4(v * t.x, v * t.y, v * t.z, v * t.w);
        red_add_v4(out + (size_t)r * dst_stride + lane * 4, o);
    }
}

// word_emb scatter: out2[rows[e], 128:428] += vals[e] * word_emb[cols[e], :]
// 300 floats = 75 float4 per row. Warp per edge.
__global__ void scatter_wemb_kernel(const int* __restrict__ rows,
                                    const int* __restrict__ cols,
                                    const float* __restrict__ vals,
                                    const float* __restrict__ we,
                                    float* __restrict__ out2, int E)
{
    int gw   = (blockIdx.x * blockDim.x + threadIdx.x) >> 5;
    int lane = threadIdx.x & 31;
    int nw   = (gridDim.x * blockDim.x) >> 5;
    const int NV = D_WEMB / 4;  // 75
    for (int e = gw; e < E; e += nw) {
        int   r = __ldg(rows + e);
        int   c = __ldg(cols + e);
        float v = __ldg(vals + e);
        const float4* src = (const float4*)(we + (size_t)c * D_WEMB);
        float* dst = out2 + (size_t)r * OUT2_STRIDE + DIM;
        #pragma unroll
        for (int j = lane; j < NV; j += 32) {
            float4 t = __ldg(src + j);
            red_add_v4(dst + j * 4,
                       make_float4(v * t.x, v * t.y, v * t.z, v * t.w));
        }
    }
}

// ---------------------------------------------------------------------------
// C[N,128] = (relu?)(A[N,K]) @ W[K,128] + bias[128]
// One block (128 threads) per row (grid-stride). W stays L1-resident (<=64KB).
template <bool RELU_A>
__global__ void gemm_bias_kernel(const float* __restrict__ A,
                                 const float* __restrict__ W,
                                 const float* __restrict__ bias,
                                 float* __restrict__ C, int N, int K)
{
    __shared__ float sA[DIM];
    int j = threadIdx.x;  // 0..127
    for (int r = blockIdx.x; r < N; r += gridDim.x) {
        if (j < K) {
            float v = A[(size_t)r * K + j];
            sA[j] = RELU_A ? fmaxf(v, 0.f) : v;
        }
        __syncthreads();
        float acc = bias[j];
        #pragma unroll 4
        for (int k = 0; k < K; k++)
            acc = fmaf(sA[k], __ldg(W + k * DIM + j), acc);
        C[(size_t)r * DIM + j] = acc;
        __syncthreads();
    }
}

// ---------------------------------------------------------------------------
// in-place row L2 normalization: p /= (||p||_2 + 1e-9). Warp per row.
__global__ void l2norm_kernel(float* __restrict__ buf, int N, int D)
{
    int row  = blockIdx.x * (blockDim.x >> 5) + (threadIdx.x >> 5);
    int lane = threadIdx.x & 31;
    if (row >= N) return;
    float* p = buf + (size_t)row * D;
    int nv = D / 4;
    float s = 0.f;
    for (int j = lane; j < nv; j += 32) {
        float4 t = ((const float4*)p)[j];
        s += t.x * t.x + t.y * t.y + t.z * t.z + t.w * t.w;
    }
    #pragma unroll
    for (int o = 16; o; o >>= 1) s += __shfl_xor_sync(0xFFFFFFFFu, s, o);
    float inv = 1.f / (sqrtf(s) + EPSN);
    for (int j = lane; j < nv; j += 32) {
        float4 t = ((float4*)p)[j];
        t.x *= inv; t.y *= inv; t.z *= inv; t.w *= inv;
        ((float4*)p)[j] = t;
    }
}

// ---------------------------------------------------------------------------
static inline int scatter_grid(int E) {
    // warp per edge, 8 warps per block
    long b = ((long)E + 7) / 8;
    return (int)b;
}

extern "C" void kernel_launch(void* const* d_in, const int* in_sizes, int n_in,
                              void* d_out, int out_size)
{
    const float* f1       = (const float*)d_in[0];
    const float* f2       = (const float*)d_in[1];
    const float* f3       = (const float*)d_in[2];
    const float* word_emb = (const float*)d_in[3];
    const int *a11r = (const int*)d_in[4],  *a11c = (const int*)d_in[5];
    const float* a11v = (const float*)d_in[6];
    const int *a22r = (const int*)d_in[7],  *a22c = (const int*)d_in[8];
    const float* a22v = (const float*)d_in[9];
    const int *a33r = (const int*)d_in[10], *a33c = (const int*)d_in[11];
    const float* a33v = (const float*)d_in[12];
    const int *a01r = (const int*)d_in[13], *a01c = (const int*)d_in[14];
    const float* a01v = (const float*)d_in[15];
    const int *a02r = (const int*)d_in[16], *a02c = (const int*)d_in[17];
    const float* a02v = (const float*)d_in[18];
    const int *a03r = (const int*)d_in[19], *a03c = (const int*)d_in[20];
    const float* a03v = (const float*)d_in[21];
    const float* W3   = (const float*)d_in[22];
    const float* b3   = (const float*)d_in[23];
    const float* W1_2 = (const float*)d_in[24];
    const float* b1_2 = (const float*)d_in[25];
    const float* W2_2 = (const float*)d_in[26];
    const float* b2_2 = (const float*)d_in[27];
    const float* W3_2 = (const float*)d_in[28];
    const float* b3_2 = (const float*)d_in[29];

    const int E11 = in_sizes[4],  E22 = in_sizes[7],  E33 = in_sizes[10];
    const int E01 = in_sizes[13], E02 = in_sizes[16], E03 = in_sizes[19];

    float* scratch = nullptr;
    cudaGetSymbolAddress((void**)&scratch, g_scratch);
    float* tmpA  = scratch + TMPA_OFF;
    float* tmpB  = scratch + TMPB_OFF;
    float* tmp2  = scratch + TMP2_OFF;
    float* tmp2b = scratch + TMP2B_OFF;
    float* tmp3  = scratch + TMP3_OFF;
    float* tmp3b = scratch + TMP3B_OFF;
    float* g1    = scratch + G1_OFF;
    float* g2    = scratch + G2_OFF;
    float* g3    = scratch + G3_OFF;
    float* g3b   = scratch + G3B_OFF;

    float* out  = (float*)d_out;
    float* out1 = out + OUT1_OFF;
    float* out2 = out + OUT2_OFF;
    float* out3 = out + OUT3_OFF;

    // zero accumulators + output (atomic destinations)
    cudaMemsetAsync(scratch, 0, (size_t)ACC_TOTAL * sizeof(float), 0);
    cudaMemsetAsync(out, 0, (size_t)out_size * sizeof(float), 0);

    const int TB = 256;

    // ---- type 1 (words) ----
    scatter128_kernel<false><<<scatter_grid(E11), TB>>>(a11r, a11c, a11v, f1, tmpA, DIM, E11);
    gemm_bias_kernel<true><<<N_WORD, DIM>>>(tmpA, W1_2, b1_2, g1, N_WORD, DIM);
    scatter128_kernel<false><<<scatter_grid(E11), TB>>>(a11r, a11c, a11v, g1, tmpB, DIM, E11);

    // ---- type 2 (entities) ----
    scatter128_kernel<false><<<scatter_grid(E22), TB>>>(a22r, a22c, a22v, f2, tmp2, DIM, E22);
    gemm_bias_kernel<true><<<N_ENT, DIM>>>(tmp2, W2_2, b2_2, g2, N_ENT, DIM);
    scatter128_kernel<false><<<scatter_grid(E22), TB>>>(a22r, a22c, a22v, g2, tmp2b, DIM, E22);

    // ---- type 3 (POS) ----
    gemm_bias_kernel<false><<<N_POS, DIM>>>(f3, W3, b3, g3, N_POS, D_POS_IN);
    scatter128_kernel<false><<<scatter_grid(E33), TB>>>(a33r, a33c, a33v, g3, tmp3, DIM, E33);
    gemm_bias_kernel<true><<<N_POS, DIM>>>(tmp3, W3_2, b3_2, g3b, N_POS, DIM);
    scatter128_kernel<false><<<scatter_grid(E33), TB>>>(a33r, a33c, a33v, g3b, tmp3b, DIM, E33);

    // ---- cross-type aggregation onto docs (relu fused into gather) ----
    scatter128_kernel<true><<<scatter_grid(E01), TB>>>(a01r, a01c, a01v, tmpB,  out1, DIM,         E01);
    scatter128_kernel<true><<<scatter_grid(E02), TB>>>(a02r, a02c, a02v, tmp2b, out2, OUT2_STRIDE, E02);
    scatter_wemb_kernel    <<<scatter_grid(E02), TB>>>(a02r, a02c, a02v, word_emb, out2, E02);
    scatter128_kernel<true><<<scatter_grid(E03), TB>>>(a03r, a03c, a03v, tmp3b, out3, DIM,         E03);

    // ---- per-row L2 normalization ----
    const int ROWS_PER_BLK = TB / 32;
    int ngrid = (N_DOC + ROWS_PER_BLK - 1) / ROWS_PER_BLK;
    l2norm_kernel<<<ngrid, TB>>>(out1, N_DOC, DIM);
    l2norm_kernel<<<ngrid, TB>>>(out2, N_DOC, OUT2_STRIDE);
    l2norm_kernel<<<ngrid, TB>>>(out3, N_DOC, DIM);
}

// round 5
// speedup vs baseline: 2.0981x; 2.0981x over previous
#include <cuda_runtime.h>
#include <math.h>

// ---------------------------------------------------------------------------
// SHINE heterogeneous GCN — CSR-ized (counting sort per call), gather-based
// SpMM (no feature atomics), register-tiled GEMM, fused doc-agg + L2 norm.
// ---------------------------------------------------------------------------
#define N_DOC    10000
#define N_WORD   20000
#define N_ENT    10000
#define N_POS    60
#define DIM      128
#define D_POS_IN 60
#define D_WEMB   300
#define EPSN     1e-9f

// Edge counts (fixed by the problem definition)
#define E11 320000
#define E22 160000
#define E33 3600
#define E01 300000
#define E02 100000
#define E03 150000
#define TOT_E (E11 + E22 + E33 + E01 + E02 + E03)   // 1,033,600

// Counter-segment bases (order: a11, a22, a33, a01, a02, a03)
#define C11 0
#define C22 (C11 + N_WORD)   // 20000
#define C33 (C22 + N_ENT)    // 30000
#define C01 (C33 + N_POS)    // 30060
#define C02 (C01 + N_DOC)    // 40060
#define C03 (C02 + N_DOC)    // 50060
#define CTOT (C03 + N_DOC)   // 60060

// Edge-buffer segment bases (same order)
#define B11 0
#define B22 (B11 + E11)
#define B33 (B22 + E22)
#define B01 (B33 + E33)
#define B02 (B01 + E01)
#define B03 (B02 + E02)

// ---------------------------------------------------------------------------
// static scratch (no allocations allowed)
__device__ __align__(16) float2 g_sorted[TOT_E];   // row-sorted (col,val)
__device__ int g_cnt[CTOT];
__device__ int g_off[CTOT];
__device__ int g_cur[CTOT];

__device__ __align__(16) float g_tmpA [N_WORD * DIM];
__device__ __align__(16) float g_tmpB [N_WORD * DIM];
__device__ __align__(16) float g_g1   [N_WORD * DIM];
__device__ __align__(16) float g_tmp2 [N_ENT  * DIM];
__device__ __align__(16) float g_tmp2b[N_ENT  * DIM];
__device__ __align__(16) float g_g2   [N_ENT  * DIM];
__device__ __align__(16) float g_tmp3 [N_POS  * DIM];
__device__ __align__(16) float g_tmp3b[N_POS  * DIM];
__device__ __align__(16) float g_g3   [N_POS  * DIM];
__device__ __align__(16) float g_g3b  [N_POS  * DIM];

struct EdgePtrs {
    const int *r11, *c11; const float *v11;
    const int *r22, *c22; const float *v22;
    const int *r33, *c33; const float *v33;
    const int *r01, *c01; const float *v01;
    const int *r02, *c02; const float *v02;
    const int *r03, *c03; const float *v03;
};

// ---------------------------------------------------------------------------
__device__ __forceinline__ float4 relu4(float4 t) {
    t.x = fmaxf(t.x, 0.f); t.y = fmaxf(t.y, 0.f);
    t.z = fmaxf(t.z, 0.f); t.w = fmaxf(t.w, 0.f);
    return t;
}
__device__ __forceinline__ void fma4(float4& a, float s, float4 t) {
    a.x = fmaf(s, t.x, a.x); a.y = fmaf(s, t.y, a.y);
    a.z = fmaf(s, t.z, a.z); a.w = fmaf(s, t.w, a.w);
}
__device__ __forceinline__ float dot4(float4 a) {
    return a.x * a.x + a.y * a.y + a.z * a.z + a.w * a.w;
}

// ---------------------------------------------------------------------------
// 1) fused histogram over all 6 adjacencies
__global__ void hist_kernel(EdgePtrs ep) {
    int e = blockIdx.x * blockDim.x + threadIdx.x;
    if (e >= TOT_E) return;
    int gi;
    if      (e < B22) gi = C11 + __ldg(ep.r11 + (e - B11));
    else if (e < B33) gi = C22 + __ldg(ep.r22 + (e - B22));
    else if (e < B01) gi = C33 + __ldg(ep.r33 + (e - B33));
    else if (e < B02) gi = C01 + __ldg(ep.r01 + (e - B01));
    else if (e < B03) gi = C02 + __ldg(ep.r02 + (e - B02));
    else              gi = C03 + __ldg(ep.r03 + (e - B03));
    atomicAdd(g_cnt + gi, 1);
}

// 2) single-block exclusive scan of the 60,060 counters
__global__ void scan_kernel() {
    __shared__ int sp[1024];
    const int tid = threadIdx.x;
    const int per = (CTOT + 1023) / 1024;   // 59
    int lo = tid * per;
    int hi = lo + per; if (hi > CTOT) hi = CTOT;
    int s = 0;
    for (int i = lo; i < hi; i++) s += g_cnt[i];
    sp[tid] = s;
    __syncthreads();
    for (int d = 1; d < 1024; d <<= 1) {
        int v = (tid >= d) ? sp[tid - d] : 0;
        __syncthreads();
        sp[tid] += v;
        __syncthreads();
    }
    int run = (tid > 0) ? sp[tid - 1] : 0;
    for (int i = lo; i < hi; i++) {
        g_off[i] = run;
        g_cur[i] = run;
        run += g_cnt[i];
    }
}

// 3) fused bucket scatter: row-sorted (col,val) records
__global__ void bucket_kernel(EdgePtrs ep) {
    int e = blockIdx.x * blockDim.x + threadIdx.x;
    if (e >= TOT_E) return;
    int r, c, cb; float v;
    if (e < B22)      { int i = e - B11; r = __ldg(ep.r11+i); c = __ldg(ep.c11+i); v = __ldg(ep.v11+i); cb = C11; }
    else if (e < B33) { int i = e - B22; r = __ldg(ep.r22+i); c = __ldg(ep.c22+i); v = __ldg(ep.v22+i); cb = C22; }
    else if (e < B01) { int i = e - B33; r = __ldg(ep.r33+i); c = __ldg(ep.c33+i); v = __ldg(ep.v33+i); cb = C33; }
    else if (e < B02) { int i = e - B01; r = __ldg(ep.r01+i); c = __ldg(ep.c01+i); v = __ldg(ep.v01+i); cb = C01; }
    else if (e < B03) { int i = e - B02; r = __ldg(ep.r02+i); c = __ldg(ep.c02+i); v = __ldg(ep.v02+i); cb = C02; }
    else              { int i = e - B03; r = __ldg(ep.r03+i); c = __ldg(ep.c03+i); v = __ldg(ep.v03+i); cb = C03; }
    int pos = atomicAdd(g_cur + cb + r, 1);
    g_sorted[pos] = make_float2(__int_as_float(c), v);
}

// ---------------------------------------------------------------------------
// gather-based SpMM row accumulator: warp-per-row, float4 per lane (D=128)
template <bool RELU>
__device__ __forceinline__ float4 spmm_row_acc(int gi, const float* __restrict__ x, int lane) {
    int s = __ldg(g_off + gi);
    int e = (gi + 1 < CTOT) ? __ldg(g_off + gi + 1) : TOT_E;
    float4 acc = make_float4(0.f, 0.f, 0.f, 0.f);
    #pragma unroll 4
    for (int k = s; k < e; ++k) {
        float2 cv = __ldg(&g_sorted[k]);
        int c = __float_as_int(cv.x);
        float4 t = __ldg((const float4*)(x + (size_t)c * DIM) + lane);
        if (RELU) t = relu4(t);
        fma4(acc, cv.y, t);
    }
    return acc;
}

// 4/6) fused layer-1 / layer-2 SpMM over all three node types
template <int LAYER>
__global__ void spmm_l_kernel(const float* __restrict__ f1, const float* __restrict__ f2) {
    int w    = (blockIdx.x * blockDim.x + threadIdx.x) >> 5;
    int lane = threadIdx.x & 31;
    if (w >= N_WORD + N_ENT + N_POS) return;
    const float* x; float* out; int gi;
    if (w < N_WORD) {
        gi  = C11 + w;
        x   = (LAYER == 1) ? f1 : g_g1;
        out = ((LAYER == 1) ? g_tmpA : g_tmpB) + (size_t)w * DIM;
    } else if (w < N_WORD + N_ENT) {
        int r = w - N_WORD;
        gi  = C22 + r;
        x   = (LAYER == 1) ? f2 : g_g2;
        out = ((LAYER == 1) ? g_tmp2 : g_tmp2b) + (size_t)r * DIM;
    } else {
        int r = w - (N_WORD + N_ENT);
        gi  = C33 + r;
        x   = (LAYER == 1) ? g_g3 : g_g3b;
        out = ((LAYER == 1) ? g_tmp3 : g_tmp3b) + (size_t)r * DIM;
    }
    float4 acc = spmm_row_acc<false>(gi, x, lane);
    ((float4*)out)[lane] = acc;
}

// ---------------------------------------------------------------------------
// register-tiled GEMM: one warp computes 4 rows x 128 cols.
// A fragments live in registers; A[r][k] broadcast via shfl; W streamed via L1.
template <bool RELU_A>
__device__ __forceinline__ void gemm4_rows(const float* __restrict__ A,
                                           const float* __restrict__ W,
                                           const float* __restrict__ bias,
                                           float* __restrict__ C,
                                           int r0, int K, int lane)
{
    float4 a0 = make_float4(0,0,0,0), a1 = a0, a2 = a0, a3 = a0;
    if (4 * lane < K) {
        a0 = *(const float4*)(A + (size_t)(r0 + 0) * K + 4 * lane);
        a1 = *(const float4*)(A + (size_t)(r0 + 1) * K + 4 * lane);
        a2 = *(const float4*)(A + (size_t)(r0 + 2) * K + 4 * lane);
        a3 = *(const float4*)(A + (size_t)(r0 + 3) * K + 4 * lane);
        if (RELU_A) { a0 = relu4(a0); a1 = relu4(a1); a2 = relu4(a2); a3 = relu4(a3); }
    }
    float4 bf = __ldg((const float4*)bias + lane);
    float4 c0 = bf, c1 = bf, c2 = bf, c3 = bf;

    for (int k = 0; k < K; k += 4) {
        int src = k >> 2;
        #pragma unroll
        for (int kk = 0; kk < 4; kk++) {
            float4 wv = __ldg((const float4*)(W + (size_t)(k + kk) * DIM) + lane);
            float s0 = __shfl_sync(0xffffffffu, ((const float*)&a0)[kk], src);
            float s1 = __shfl_sync(0xffffffffu, ((const float*)&a1)[kk], src);
            float s2 = __shfl_sync(0xffffffffu, ((const float*)&a2)[kk], src);
            float s3 = __shfl_sync(0xffffffffu, ((const float*)&a3)[kk], src);
            fma4(c0, s0, wv); fma4(c1, s1, wv); fma4(c2, s2, wv); fma4(c3, s3, wv);
        }
    }
    *((float4*)(C + (size_t)(r0 + 0) * DIM) + lane) = c0;
    *((float4*)(C + (size_t)(r0 + 1) * DIM) + lane) = c1;
    *((float4*)(C + (size_t)(r0 + 2) * DIM) + lane) = c2;
    *((float4*)(C + (size_t)(r0 + 3) * DIM) + lane) = c3;
}

// POS layer-1 projection: g3 = f3 @ W3 + b3 (no input relu), 60x60x128
__global__ void gemm_pos1_kernel(const float* __restrict__ f3,
                                 const float* __restrict__ W3,
                                 const float* __restrict__ b3) {
    int w    = (blockIdx.x * blockDim.x + threadIdx.x) >> 5;
    int lane = threadIdx.x & 31;
    if (w >= N_POS / 4) return;
    gemm4_rows<false>(f3, W3, b3, g_g3, 4 * w, D_POS_IN, lane);
}

// fused layer-2 projections for all three types (relu on input): K=128
__global__ void gemm_l2_kernel(const float* __restrict__ W1, const float* __restrict__ b1,
                               const float* __restrict__ W2, const float* __restrict__ b2,
                               const float* __restrict__ Wp, const float* __restrict__ bp) {
    int w    = (blockIdx.x * blockDim.x + threadIdx.x) >> 5;
    int lane = threadIdx.x & 31;
    const int WW = N_WORD / 4, WE = WW + N_ENT / 4, WP = WE + N_POS / 4;  // 5000, 7500, 7515
    if (w >= WP) return;
    if (w < WW)       gemm4_rows<true>(g_tmpA, W1, b1, g_g1,  4 * w,        DIM, lane);
    else if (w < WE)  gemm4_rows<true>(g_tmp2, W2, b2, g_g2,  4 * (w - WW), DIM, lane);
    else              gemm4_rows<true>(g_tmp3, Wp, bp, g_g3b, 4 * (w - WE), DIM, lane);
}

// ---------------------------------------------------------------------------
// 7) fused doc aggregation + relu(source) + L2 normalization (all 3 outputs)
__global__ void docagg_kernel(const float* __restrict__ word_emb, float* __restrict__ out) {
    int w    = (blockIdx.x * blockDim.x + threadIdx.x) >> 5;
    int lane = threadIdx.x & 31;
    if (w >= 3 * N_DOC) return;
    float* out1 = out;
    float* out2 = out + (size_t)N_DOC * DIM;
    float* out3 = out2 + (size_t)N_DOC * (DIM + D_WEMB);

    if (w < N_DOC || w >= 2 * N_DOC) {
        // 128-wide branches (words -> out1, POS -> out3)
        bool first = (w < N_DOC);
        int row = first ? w : (w - 2 * N_DOC);
        int gi  = first ? (C01 + row) : (C03 + row);
        const float* x = first ? g_tmpB : g_tmp3b;
        float4 acc = spmm_row_acc<true>(gi, x, lane);
        float ss = dot4(acc);
        #pragma unroll
        for (int o = 16; o; o >>= 1) ss += __shfl_xor_sync(0xffffffffu, ss, o);
        float inv = 1.f / (sqrtf(ss) + EPSN);
        float4 r = make_float4(acc.x * inv, acc.y * inv, acc.z * inv, acc.w * inv);
        float* dst = (first ? out1 : out3) + (size_t)row * DIM;
        ((float4*)dst)[lane] = r;
    } else {
        // entities -> out2: 128 feature cols + 300 word_emb cols, norm over 428
        int row = w - N_DOC;
        int gi = C02 + row;
        int s = __ldg(g_off + gi);
        int e = __ldg(g_off + gi + 1);   // gi+1 < CTOT always for this segment
        float4 aF = make_float4(0,0,0,0), w0 = aF, w1 = aF, w2 = aF;
        #pragma unroll 2
        for (int k = s; k < e; ++k) {
            float2 cv = __ldg(&g_sorted[k]);
            int c = __float_as_int(cv.x);
            float v = cv.y;
            float4 t = relu4(__ldg((const float4*)(g_tmp2b + (size_t)c * DIM) + lane));
            fma4(aF, v, t);
            const float4* ws = (const float4*)(word_emb + (size_t)c * D_WEMB); // 75 float4
            fma4(w0, v, __ldg(ws + lane));
            fma4(w1, v, __ldg(ws + lane + 32));
            if (lane < 11) fma4(w2, v, __ldg(ws + lane + 64));
        }
        float ss = dot4(aF) + dot4(w0) + dot4(w1);
        if (lane < 11) ss += dot4(w2);
        #pragma unroll
        for (int o = 16; o; o >>= 1) ss += __shfl_xor_sync(0xffffffffu, ss, o);
        float inv = 1.f / (sqrtf(ss) + EPSN);
        float* rowp = out2 + (size_t)row * (DIM + D_WEMB);
        ((float4*)rowp)[lane] = make_float4(aF.x*inv, aF.y*inv, aF.z*inv, aF.w*inv);
        float4* wr = (float4*)(rowp + DIM);
        wr[lane]      = make_float4(w0.x*inv, w0.y*inv, w0.z*inv, w0.w*inv);
        wr[lane + 32] = make_float4(w1.x*inv, w1.y*inv, w1.z*inv, w1.w*inv);
        if (lane < 11)
            wr[lane + 64] = make_float4(w2.x*inv, w2.y*inv, w2.z*inv, w2.w*inv);
    }
}

// ---------------------------------------------------------------------------
extern "C" void kernel_launch(void* const* d_in, const int* in_sizes, int n_in,
                              void* d_out, int out_size)
{
    const float* f1       = (const float*)d_in[0];
    const float* f2       = (const float*)d_in[1];
    const float* f3       = (const float*)d_in[2];
    const float* word_emb = (const float*)d_in[3];

    EdgePtrs ep;
    ep.r11 = (const int*)d_in[4];  ep.c11 = (const int*)d_in[5];  ep.v11 = (const float*)d_in[6];
    ep.r22 = (const int*)d_in[7];  ep.c22 = (const int*)d_in[8];  ep.v22 = (const float*)d_in[9];
    ep.r33 = (const int*)d_in[10]; ep.c33 = (const int*)d_in[11]; ep.v33 = (const float*)d_in[12];
    ep.r01 = (const int*)d_in[13]; ep.c01 = (const int*)d_in[14]; ep.v01 = (const float*)d_in[15];
    ep.r02 = (const int*)d_in[16]; ep.c02 = (const int*)d_in[17]; ep.v02 = (const float*)d_in[18];
    ep.r03 = (const int*)d_in[19]; ep.c03 = (const int*)d_in[20]; ep.v03 = (const float*)d_in[21];

    const float* W3   = (const float*)d_in[22];
    const float* b3   = (const float*)d_in[23];
    const float* W1_2 = (const float*)d_in[24];
    const float* b1_2 = (const float*)d_in[25];
    const float* W2_2 = (const float*)d_in[26];
    const float* b2_2 = (const float*)d_in[27];
    const float* W3_2 = (const float*)d_in[28];
    const float* b3_2 = (const float*)d_in[29];

    void* cnt_addr = nullptr;
    cudaGetSymbolAddress(&cnt_addr, g_cnt);

    const int TB = 256;
    const int GRID_E    = (TOT_E + TB - 1) / TB;                           // 4038
    const int GRID_SPMM = ((N_WORD + N_ENT + N_POS) * 32 + TB - 1) / TB;   // 3758
    const int GRID_GEMM = (((N_WORD + N_ENT + N_POS) / 4) * 32 + TB - 1) / TB; // 940
    const int GRID_DOC  = (3 * N_DOC * 32 + TB - 1) / TB;                  // 3750

    // CSR build (counting sort), shared by both layers
    cudaMemsetAsync(cnt_addr, 0, CTOT * sizeof(int), 0);
    gemm_pos1_kernel<<<1, 512>>>(f3, W3, b3);       // independent, tiny
    hist_kernel<<<GRID_E, TB>>>(ep);
    scan_kernel<<<1, 1024>>>();
    bucket_kernel<<<GRID_E, TB>>>(ep);

    // layer 1 SpMM (all types), layer 2 projection, layer 2 SpMM
    spmm_l_kernel<1><<<GRID_SPMM, TB>>>(f1, f2);
    gemm_l2_kernel<<<GRID_GEMM, TB>>>(W1_2, b1_2, W2_2, b2_2, W3_2, b3_2);
    spmm_l_kernel<2><<<GRID_SPMM, TB>>>(f1, f2);

    // doc aggregation + relu + wemb concat + L2 norm, writes every output elem
    docagg_kernel<<<GRID_DOC, TB>>>(word_emb, (float*)d_out);
}

// round 7
// speedup vs baseline: 2.3974x; 1.1426x over previous
#include <cuda_runtime.h>
#include <cuda_fp16.h>
#include <math.h>

// ---------------------------------------------------------------------------
// SHINE heterogeneous GCN — CSR counting sort, fp16-staged gather SpMM
// (fp32 accumulate), register-tiled GEMM, fused doc-agg + L2 norm.
// ---------------------------------------------------------------------------
#define N_DOC    10000
#define N_WORD   20000
#define N_ENT    10000
#define N_POS    60
#define DIM      128
#define D_POS_IN 60
#define D_WEMB   300
#define EPSN     1e-9f

#define E11 320000
#define E22 160000
#define E33 3600
#define E01 300000
#define E02 100000
#define E03 150000
#define TOT_E (E11 + E22 + E33 + E01 + E02 + E03)   // 1,033,600

// Counter-segment bases (order: a11, a22, a33, a01, a02, a03)
#define C11 0
#define C22 (C11 + N_WORD)   // 20000
#define C33 (C22 + N_ENT)    // 30000
#define C01 (C33 + N_POS)    // 30060
#define C02 (C01 + N_DOC)    // 40060
#define C03 (C02 + N_DOC)    // 50060
#define CTOT (C03 + N_DOC)   // 60060

// Edge-buffer segment bases
#define B11 0
#define B22 (B11 + E11)
#define B33 (B22 + E22)
#define B01 (B33 + E33)
#define B02 (B01 + E01)
#define B03 (B02 + E02)

// ---------------------------------------------------------------------------
// static scratch
__device__ __align__(16) float2 g_sorted[TOT_E];   // row-sorted (col_bits, val)
__device__ __align__(16) int    g_cnt[CTOT];
__device__ __align__(16) int    g_off[CTOT];       // after bucket: inclusive prefix

// fp16-staged gather sources
__device__ __align__(16) __half g_f1h  [N_WORD * DIM];
__device__ __align__(16) __half g_f2h  [N_ENT  * DIM];
__device__ __align__(16) __half g_wembh[N_ENT  * D_WEMB];
__device__ __align__(16) __half g_g1   [N_WORD * DIM];
__device__ __align__(16) __half g_g2   [N_ENT  * DIM];
__device__ __align__(16) __half g_g3   [N_POS  * DIM];
__device__ __align__(16) __half g_g3b  [N_POS  * DIM];
__device__ __align__(16) __half g_tmpB [N_WORD * DIM];
__device__ __align__(16) __half g_tmp2b[N_ENT  * DIM];
__device__ __align__(16) __half g_tmp3b[N_POS  * DIM];

// fp32 GEMM inputs (read linearly, not gathered)
__device__ __align__(16) float g_tmpA[N_WORD * DIM];
__device__ __align__(16) float g_tmp2[N_ENT  * DIM];
__device__ __align__(16) float g_tmp3[N_POS  * DIM];

struct EdgePtrs {
    const int *r11, *c11; const float *v11;
    const int *r22, *c22; const float *v22;
    const int *r33, *c33; const float *v33;
    const int *r01, *c01; const float *v01;
    const int *r02, *c02; const float *v02;
    const int *r03, *c03; const float *v03;
};

// ---------------------------------------------------------------------------
__device__ __forceinline__ float4 relu4(float4 t) {
    t.x = fmaxf(t.x, 0.f); t.y = fmaxf(t.y, 0.f);
    t.z = fmaxf(t.z, 0.f); t.w = fmaxf(t.w, 0.f);
    return t;
}
__device__ __forceinline__ void fma4(float4& a, float s, float4 t) {
    a.x = fmaf(s, t.x, a.x); a.y = fmaf(s, t.y, a.y);
    a.z = fmaf(s, t.z, a.z); a.w = fmaf(s, t.w, a.w);
}
__device__ __forceinline__ float dot4(float4 a) {
    return a.x * a.x + a.y * a.y + a.z * a.z + a.w * a.w;
}
// 8B load of 4 halves -> float4
__device__ __forceinline__ float4 ldg_h4(const __half* base, int unit) {
    uint2 u = __ldg((const uint2*)base + unit);
    __half2 a = *reinterpret_cast<__half2*>(&u.x);
    __half2 b = *reinterpret_cast<__half2*>(&u.y);
    float2 fa = __half22float2(a), fb = __half22float2(b);
    return make_float4(fa.x, fa.y, fb.x, fb.y);
}
__device__ __forceinline__ void st_h4(__half* base, int unit, float4 v) {
    __half2 a = __floats2half2_rn(v.x, v.y);
    __half2 b = __floats2half2_rn(v.z, v.w);
    uint2 u;
    u.x = *reinterpret_cast<unsigned*>(&a);
    u.y = *reinterpret_cast<unsigned*>(&b);
    ((uint2*)base)[unit] = u;
}

// ---------------------------------------------------------------------------
// register-tiled GEMM: one warp computes 4 rows x 128 cols, output fp32 or fp16
__device__ __forceinline__ void gemm_store(float* p, int lane, float4 v) {
    ((float4*)p)[lane] = v;
}
__device__ __forceinline__ void gemm_store(__half* p, int lane, float4 v) {
    st_h4(p, lane, v);
}

template <bool RELU_A, typename OutT>
__device__ __forceinline__ void gemm4_rows(const float* __restrict__ A,
                                           const float* __restrict__ W,
                                           const float* __restrict__ bias,
                                           OutT* __restrict__ C,
                                           int r0, int K, int lane)
{
    float4 a0 = make_float4(0,0,0,0), a1 = a0, a2 = a0, a3 = a0;
    if (4 * lane < K) {
        a0 = *(const float4*)(A + (size_t)(r0 + 0) * K + 4 * lane);
        a1 = *(const float4*)(A + (size_t)(r0 + 1) * K + 4 * lane);
        a2 = *(const float4*)(A + (size_t)(r0 + 2) * K + 4 * lane);
        a3 = *(const float4*)(A + (size_t)(r0 + 3) * K + 4 * lane);
        if (RELU_A) { a0 = relu4(a0); a1 = relu4(a1); a2 = relu4(a2); a3 = relu4(a3); }
    }
    float4 bf = __ldg((const float4*)bias + lane);
    float4 c0 = bf, c1 = bf, c2 = bf, c3 = bf;

    for (int k = 0; k < K; k += 4) {
        int src = k >> 2;
        #pragma unroll
        for (int kk = 0; kk < 4; kk++) {
            float4 wv = __ldg((const float4*)(W + (size_t)(k + kk) * DIM) + lane);
            float s0 = __shfl_sync(0xffffffffu, ((const float*)&a0)[kk], src);
            float s1 = __shfl_sync(0xffffffffu, ((const float*)&a1)[kk], src);
            float s2 = __shfl_sync(0xffffffffu, ((const float*)&a2)[kk], src);
            float s3 = __shfl_sync(0xffffffffu, ((const float*)&a3)[kk], src);
            fma4(c0, s0, wv); fma4(c1, s1, wv); fma4(c2, s2, wv); fma4(c3, s3, wv);
        }
    }
    gemm_store(C + (size_t)(r0 + 0) * DIM, lane, c0);
    gemm_store(C + (size_t)(r0 + 1) * DIM, lane, c1);
    gemm_store(C + (size_t)(r0 + 2) * DIM, lane, c2);
    gemm_store(C + (size_t)(r0 + 3) * DIM, lane, c3);
}

// ---------------------------------------------------------------------------
// 0) prep: zero counters + convert f1/f2/word_emb to fp16 + POS layer-1 GEMM
#define CNT4 (CTOT / 4)              // 15015
#define F1U  (N_WORD * DIM / 4)      // 640000
#define F2U  (N_ENT  * DIM / 4)      // 320000
#define WEU  (N_ENT  * D_WEMB / 4)   // 750000
#define PREP_UNITS (CNT4 + F1U + F2U + WEU)

__global__ void prep_kernel(const float* __restrict__ f1, const float* __restrict__ f2,
                            const float* __restrict__ wemb, const float* __restrict__ f3,
                            const float* __restrict__ W3, const float* __restrict__ b3)
{
    if (blockIdx.x == 0) {
        int lane = threadIdx.x & 31;
        for (int w = threadIdx.x >> 5; w < N_POS / 4; w += blockDim.x >> 5)
            gemm4_rows<false>(f3, W3, b3, g_g3, 4 * w, D_POS_IN, lane);
        return;
    }
    int stride = (gridDim.x - 1) * blockDim.x;
    for (int u = (blockIdx.x - 1) * blockDim.x + threadIdx.x; u < PREP_UNITS; u += stride) {
        if (u < CNT4) {
            ((int4*)g_cnt)[u] = make_int4(0, 0, 0, 0);
        } else if (u < CNT4 + F1U) {
            int i = u - CNT4;
            st_h4(g_f1h, i, __ldg((const float4*)f1 + i));
        } else if (u < CNT4 + F1U + F2U) {
            int i = u - (CNT4 + F1U);
            st_h4(g_f2h, i, __ldg((const float4*)f2 + i));
        } else {
            int i = u - (CNT4 + F1U + F2U);
            st_h4(g_wembh, i, __ldg((const float4*)wemb + i));
        }
    }
}

// ---------------------------------------------------------------------------
// 1) fused histogram over all 6 adjacencies
__global__ void hist_kernel(EdgePtrs ep) {
    int e = blockIdx.x * blockDim.x + threadIdx.x;
    if (e >= TOT_E) return;
    int gi;
    if      (e < B22) gi = C11 + __ldg(ep.r11 + (e - B11));
    else if (e < B33) gi = C22 + __ldg(ep.r22 + (e - B22));
    else if (e < B01) gi = C33 + __ldg(ep.r33 + (e - B33));
    else if (e < B02) gi = C01 + __ldg(ep.r01 + (e - B01));
    else if (e < B03) gi = C02 + __ldg(ep.r02 + (e - B02));
    else              gi = C03 + __ldg(ep.r03 + (e - B03));
    atomicAdd(g_cnt + gi, 1);
}

// 2) single-block exclusive scan of the counters -> g_off
__global__ void scan_kernel() {
    __shared__ int sp[1024];
    const int tid = threadIdx.x;
    const int per = (CTOT + 1023) / 1024;   // 59
    int lo = tid * per;
    int hi = lo + per; if (hi > CTOT) hi = CTOT;
    if (lo > CTOT) lo = CTOT;
    int s = 0;
    for (int i = lo; i < hi; i++) s += g_cnt[i];
    sp[tid] = s;
    __syncthreads();
    for (int d = 1; d < 1024; d <<= 1) {
        int v = (tid >= d) ? sp[tid - d] : 0;
        __syncthreads();
        sp[tid] += v;
        __syncthreads();
    }
    int run = (tid > 0) ? sp[tid - 1] : 0;
    for (int i = lo; i < hi; i++) {
        g_off[i] = run;
        run += g_cnt[i];
    }
}

// 3) bucket scatter; bumps g_off in place (afterwards g_off = inclusive prefix)
__global__ void bucket_kernel(EdgePtrs ep) {
    int e = blockIdx.x * blockDim.x + threadIdx.x;
    if (e >= TOT_E) return;
    int r, c, cb; float v;
    if (e < B22)      { int i = e - B11; r = __ldg(ep.r11+i); c = __ldg(ep.c11+i); v = __ldg(ep.v11+i); cb = C11; }
    else if (e < B33) { int i = e - B22; r = __ldg(ep.r22+i); c = __ldg(ep.c22+i); v = __ldg(ep.v22+i); cb = C22; }
    else if (e < B01) { int i = e - B33; r = __ldg(ep.r33+i); c = __ldg(ep.c33+i); v = __ldg(ep.v33+i); cb = C33; }
    else if (e < B02) { int i = e - B01; r = __ldg(ep.r01+i); c = __ldg(ep.c01+i); v = __ldg(ep.v01+i); cb = C01; }
    else if (e < B03) { int i = e - B02; r = __ldg(ep.r02+i); c = __ldg(ep.c02+i); v = __ldg(ep.v02+i); cb = C02; }
    else              { int i = e - B03; r = __ldg(ep.r03+i); c = __ldg(ep.c03+i); v = __ldg(ep.v03+i); cb = C03; }
    int pos = atomicAdd(g_off + cb + r, 1);
    g_sorted[pos] = make_float2(__int_as_float(c), v);
}

// ---------------------------------------------------------------------------
// gather SpMM row accumulator over fp16 source; warp-per-row, float4/lane
template <bool RELU>
__device__ __forceinline__ float4 spmm_row_acc_h(int gi, const __half* __restrict__ x, int lane) {
    int s = (gi == 0) ? 0 : __ldg(g_off + gi - 1);
    int e = __ldg(g_off + gi);
    float4 acc0 = make_float4(0.f, 0.f, 0.f, 0.f);
    float4 acc1 = acc0;
    int k = s;
    for (; k + 1 < e; k += 2) {
        float2 cv0 = __ldg(&g_sorted[k]);
        float2 cv1 = __ldg(&g_sorted[k + 1]);
        int c0 = __float_as_int(cv0.x);
        int c1 = __float_as_int(cv1.x);
        float4 t0 = ldg_h4(x + (size_t)c0 * DIM, lane);
        float4 t1 = ldg_h4(x + (size_t)c1 * DIM, lane);
        if (RELU) { t0 = relu4(t0); t1 = relu4(t1); }
        fma4(acc0, cv0.y, t0);
        fma4(acc1, cv1.y, t1);
    }
    if (k < e) {
        float2 cv = __ldg(&g_sorted[k]);
        int c = __float_as_int(cv.x);
        float4 t = ldg_h4(x + (size_t)c * DIM, lane);
        if (RELU) t = relu4(t);
        fma4(acc0, cv.y, t);
    }
    acc0.x += acc1.x; acc0.y += acc1.y; acc0.z += acc1.z; acc0.w += acc1.w;
    return acc0;
}

// 4/6) fused layer-1 / layer-2 SpMM over all three node types
template <int LAYER>
__global__ void spmm_l_kernel() {
    int w    = (blockIdx.x * blockDim.x + threadIdx.x) >> 5;
    int lane = threadIdx.x & 31;
    if (w >= N_WORD + N_ENT + N_POS) return;
    const __half* x; void* outp; int gi;
    if (w < N_WORD) {
        gi = C11 + w;
        x = (LAYER == 1) ? g_f1h : g_g1;
        outp = (LAYER == 1) ? (void*)(g_tmpA + (size_t)w * DIM)
                            : (void*)(g_tmpB + (size_t)w * DIM);
    } else if (w < N_WORD + N_ENT) {
        int r = w - N_WORD;
        gi = C22 + r;
        x = (LAYER == 1) ? g_f2h : g_g2;
        outp = (LAYER == 1) ? (void*)(g_tmp2 + (size_t)r * DIM)
                            : (void*)(g_tmp2b + (size_t)r * DIM);
    } else {
        int r = w - (N_WORD + N_ENT);
        gi = C33 + r;
        x = (LAYER == 1) ? g_g3 : g_g3b;
        outp = (LAYER == 1) ? (void*)(g_tmp3 + (size_t)r * DIM)
                            : (void*)(g_tmp3b + (size_t)r * DIM);
    }
    float4 acc = spmm_row_acc_h<false>(gi, x, lane);
    if (LAYER == 1) ((float4*)outp)[lane] = acc;
    else            st_h4((__half*)outp, lane, acc);
}

// 5) fused layer-2 projections for all three types (relu on input): K=128
__global__ void gemm_l2_kernel(const float* __restrict__ W1, const float* __restrict__ b1,
                               const float* __restrict__ W2, const float* __restrict__ b2,
                               const float* __restrict__ Wp, const float* __restrict__ bp) {
    int w    = (blockIdx.x * blockDim.x + threadIdx.x) >> 5;
    int lane = threadIdx.x & 31;
    const int WW = N_WORD / 4, WE = WW + N_ENT / 4, WP = WE + N_POS / 4;
    if (w >= WP) return;
    if (w < WW)       gemm4_rows<true>(g_tmpA, W1, b1, g_g1,  4 * w,        DIM, lane);
    else if (w < WE)  gemm4_rows<true>(g_tmp2, W2, b2, g_g2,  4 * (w - WW), DIM, lane);
    else              gemm4_rows<true>(g_tmp3, Wp, bp, g_g3b, 4 * (w - WE), DIM, lane);
}

// ---------------------------------------------------------------------------
// 7) fused doc aggregation + relu(source) + wemb concat + L2 norm
__global__ void docagg_kernel(float* __restrict__ out) {
    int w    = (blockIdx.x * blockDim.x + threadIdx.x) >> 5;
    int lane = threadIdx.x & 31;
    if (w >= 3 * N_DOC) return;
    float* out1 = out;
    float* out2 = out + (size_t)N_DOC * DIM;
    float* out3 = out2 + (size_t)N_DOC * (DIM + D_WEMB);

    if (w < N_DOC || w >= 2 * N_DOC) {
        bool first = (w < N_DOC);
        int row = first ? w : (w - 2 * N_DOC);
        int gi  = first ? (C01 + row) : (C03 + row);
        const __half* x = first ? g_tmpB : g_tmp3b;
        float4 acc = spmm_row_acc_h<true>(gi, x, lane);
        float ss = dot4(acc);
        #pragma unroll
        for (int o = 16; o; o >>= 1) ss += __shfl_xor_sync(0xffffffffu, ss, o);
        float inv = 1.f / (sqrtf(ss) + EPSN);
        float* dst = (first ? out1 : out3) + (size_t)row * DIM;
        ((float4*)dst)[lane] = make_float4(acc.x*inv, acc.y*inv, acc.z*inv, acc.w*inv);
    } else {
        // entities -> out2: 128 feature cols + 300 word_emb cols, norm over 428
        int row = w - N_DOC;
        int gi = C02 + row;
        int s = __ldg(g_off + gi - 1);
        int e = __ldg(g_off + gi);
        float4 aF = make_float4(0,0,0,0), w0 = aF, w1 = aF, w2 = aF;
        #pragma unroll 2
        for (int k = s; k < e; ++k) {
            float2 cv = __ldg(&g_sorted[k]);
            int c = __float_as_int(cv.x);
            float v = cv.y;
            float4 t = relu4(ldg_h4(g_tmp2b + (size_t)c * DIM, lane));
            fma4(aF, v, t);
            const __half* ws = g_wembh + (size_t)c * D_WEMB;  // 75 h4-units
            fma4(w0, v, ldg_h4(ws, lane));
            fma4(w1, v, ldg_h4(ws, lane + 32));
            if (lane < 11) fma4(w2, v, ldg_h4(ws, lane + 64));
        }
        float ss = dot4(aF) + dot4(w0) + dot4(w1);
        if (lane < 11) ss += dot4(w2);
        #pragma unroll
        for (int o = 16; o; o >>= 1) ss += __shfl_xor_sync(0xffffffffu, ss, o);
        float inv = 1.f / (sqrtf(ss) + EPSN);
        float* rowp = out2 + (size_t)row * (DIM + D_WEMB);
        ((float4*)rowp)[lane] = make_float4(aF.x*inv, aF.y*inv, aF.z*inv, aF.w*inv);
        float4* wr = (float4*)(rowp + DIM);
        wr[lane]      = make_float4(w0.x*inv, w0.y*inv, w0.z*inv, w0.w*inv);
        wr[lane + 32] = make_float4(w1.x*inv, w1.y*inv, w1.z*inv, w1.w*inv);
        if (lane < 11)
            wr[lane + 64] = make_float4(w2.x*inv, w2.y*inv, w2.z*inv, w2.w*inv);
    }
}

// ---------------------------------------------------------------------------
extern "C" void kernel_launch(void* const* d_in, const int* in_sizes, int n_in,
                              void* d_out, int out_size)
{
    const float* f1       = (const float*)d_in[0];
    const float* f2       = (const float*)d_in[1];
    const float* f3       = (const float*)d_in[2];
    const float* word_emb = (const float*)d_in[3];

    EdgePtrs ep;
    ep.r11 = (const int*)d_in[4];  ep.c11 = (const int*)d_in[5];  ep.v11 = (const float*)d_in[6];
    ep.r22 = (const int*)d_in[7];  ep.c22 = (const int*)d_in[8];  ep.v22 = (const float*)d_in[9];
    ep.r33 = (const int*)d_in[10]; ep.c33 = (const int*)d_in[11]; ep.v33 = (const float*)d_in[12];
    ep.r01 = (const int*)d_in[13]; ep.c01 = (const int*)d_in[14]; ep.v01 = (const float*)d_in[15];
    ep.r02 = (const int*)d_in[16]; ep.c02 = (const int*)d_in[17]; ep.v02 = (const float*)d_in[18];
    ep.r03 = (const int*)d_in[19]; ep.c03 = (const int*)d_in[20]; ep.v03 = (const float*)d_in[21];

    const float* W3   = (const float*)d_in[22];
    const float* b3   = (const float*)d_in[23];
    const float* W1_2 = (const float*)d_in[24];
    const float* b1_2 = (const float*)d_in[25];
    const float* W2_2 = (const float*)d_in[26];
    const float* b2_2 = (const float*)d_in[27];
    const float* W3_2 = (const float*)d_in[28];
    const float* b3_2 = (const float*)d_in[29];

    const int TB = 256;
    const int GRID_PREP = 2048 + 1;
    const int GRID_E    = (TOT_E + TB - 1) / TB;
    const int GRID_SPMM = ((N_WORD + N_ENT + N_POS) * 32 + TB - 1) / TB;
    const int GRID_GEMM = (((N_WORD + N_ENT + N_POS) / 4) * 32 + TB - 1) / TB;
    const int GRID_DOC  = (3 * N_DOC * 32 + TB - 1) / TB;

    prep_kernel<<<GRID_PREP, TB>>>(f1, f2, word_emb, f3, W3, b3);
    hist_kernel<<<GRID_E, TB>>>(ep);
    scan_kernel<<<1, 1024>>>();
    bucket_kernel<<<GRID_E, TB>>>(ep);

    spmm_l_kernel<1><<<GRID_SPMM, TB>>>();
    gemm_l2_kernel<<<GRID_GEMM, TB>>>(W1_2, b1_2, W2_2, b2_2, W3_2, b3_2);
    spmm_l_kernel<2><<<GRID_SPMM, TB>>>();

    docagg_kernel<<<GRID_DOC, TB>>>((float*)d_out);
}